// round 2
// baseline (speedup 1.0000x reference)
#include <cuda_runtime.h>

#define DEPTH 8
#define DIM 16
#define NPTS 8
#define IN_DIM 1024
#define INNER 64
#define RAYS_PER_BLOCK 32
#define THREADS 256

// smem layout (in floats)
#define FEAT_STRIDE 1028                 // 1024 + 4 pad, keeps 16B alignment per row
#define OFF_FEAT 0
#define OFF_BUF (32 * FEAT_STRIDE)       // 32896
#define BUF_FLOATS 16896                 // >= max(128*132=16896, 256*64=16384, 64*64=4096)
#define OFF_H1 (OFF_BUF + BUF_FLOATS)    // 49792
#define OFF_H2 (OFF_H1 + 2048)           // 51840
#define OFF_NODES (OFF_H2 + 2048)        // 53888 (128 ints)
#define SMEM_FLOATS (OFF_NODES + 128)    // 54016
#define SMEM_BYTES (SMEM_FLOATS * 4)     // 216064 B

__global__ void __launch_bounds__(THREADS, 1) nbvh_kernel(
    const float* __restrict__ orig, const float* __restrict__ endp,
    const int* __restrict__ history32,
    const float* __restrict__ nodes_min, const float* __restrict__ nodes_extent,
    const float* __restrict__ emb,
    const float* __restrict__ W1, const float* __restrict__ W2,
    const float* __restrict__ W3,
    float* __restrict__ out)
{
    extern __shared__ float sm[];
    float* feat = sm + OFF_FEAT;
    float* buf  = sm + OFF_BUF;
    float* h1   = sm + OFF_H1;
    float* h2   = sm + OFF_H2;
    int*   nodes_s = (int*)(sm + OFF_NODES);

    const int tid  = threadIdx.x;
    const int ray0 = blockIdx.x * RAYS_PER_BLOCK;

    // Detect history dtype: int64 (little-endian, hi words are 0 since idx < 2^19)
    // vs int32. Stride 2 if int64, 1 if int32. Safe: all reads stay within the
    // int32-interpretation bounds.
    const int hstride =
        (history32[1] == 0 && history32[3] == 0 &&
         history32[5] == 0 && history32[7] == 0) ? 2 : 1;

    // ---------------- Phase 1: features (two halves of 16 rays) ----------------
    for (int half = 0; half < 2; ++half) {
        const int rbase = ray0 + half * 16;

        if (tid < 128) {
            int lray = tid >> 3, d = tid & 7;
            nodes_s[tid] = history32[(size_t)((rbase + lray) * 8 + d) * hstride];
        }
        __syncthreads();

        // stage 128 emb rows (512B each) into buf, padded row stride 132 floats
        {
            const float4* emb4 = (const float4*)emb;
            for (int i = tid; i < 128 * 32; i += THREADS) {
                int row = i >> 5, l = i & 31;
                float4 v = emb4[(long long)nodes_s[row] * 32 + l];
                *(float4*)(buf + row * 132 + l * 4) = v;
            }
        }
        __syncthreads();

        // compute features: 2 threads per (ray,depth) row, split over feature quads
        {
            int row = tid >> 1, fh = tid & 1;
            int lray = row >> 3, d = row & 7;
            int ray  = rbase + lray;
            int node = nodes_s[row];

            float ox = orig[ray * 3 + 0], oy = orig[ray * 3 + 1], oz = orig[ray * 3 + 2];
            float ex = endp[ray * 3 + 0], ey = endp[ray * 3 + 1], ez = endp[ray * 3 + 2];
            float nx = nodes_min[node * 3 + 0], ny = nodes_min[node * 3 + 1], nz = nodes_min[node * 3 + 2];
            float sx = nodes_extent[node * 3 + 0], sy = nodes_extent[node * 3 + 1], sz = nodes_extent[node * 3 + 2];

            float pox = fminf(fmaxf((ox - nx) / sx, 0.f), 1.f);
            float poy = fminf(fmaxf((oy - ny) / sy, 0.f), 1.f);
            float poz = fminf(fmaxf((oz - nz) / sz, 0.f), 1.f);
            float pex = fminf(fmaxf((ex - nx) / sx, 0.f), 1.f);
            float pey = fminf(fmaxf((ey - ny) / sy, 0.f), 1.f);
            float pez = fminf(fmaxf((ez - nz) / sz, 0.f), 1.f);
            float dx = pex - pox, dy = pey - poy, dz = pez - poz;

            float* frow = feat + (half * 16 + lray) * FEAT_STRIDE + d * (NPTS * DIM);

            #pragma unroll
            for (int f4 = 0; f4 < 2; ++f4) {
                int fo = (fh * 2 + f4) * 4;   // float offset within 16-dim feature
                float4 e[8];
                #pragma unroll
                for (int k = 0; k < 8; ++k)
                    e[k] = *(const float4*)(buf + row * 132 + k * 16 + fo);

                #pragma unroll
                for (int p = 0; p < 8; ++p) {
                    float t = (float)p * (1.0f / 7.0f);
                    float x = pox + dx * t, y = poy + dy * t, z = poz + dz * t;
                    float mx = 1.f - x, my = 1.f - y, mz = 1.f - z;
                    float w0 = mx * my * mz, w1v = x * my * mz;
                    float w2v = mx * y * mz, w3v = mx * my * z;
                    float w4 = x * my * z,  w5 = mx * y * z;
                    float w6 = x * y * mz,  w7 = x * y * z;
                    float4 a;
                    #define TRI(c) a.c = fmaf(w7, e[7].c, fmaf(w6, e[6].c, fmaf(w5, e[5].c, \
                                    fmaf(w4, e[4].c, fmaf(w3v, e[3].c, fmaf(w2v, e[2].c,   \
                                    fmaf(w1v, e[1].c, w0 * e[0].c)))))))
                    TRI(x); TRI(y); TRI(z); TRI(w);
                    #undef TRI
                    *(float4*)(frow + p * DIM + fo) = a;
                }
            }
        }
        __syncthreads();
    }

    // ---------------- Phase 2: h1 = relu(feat @ W1), K-tiled ----------------
    const int warp = tid >> 5, lane = tid & 31;
    float2 acc[4];
    #pragma unroll
    for (int r = 0; r < 4; ++r) acc[r] = make_float2(0.f, 0.f);

    for (int tile = 0; tile < 4; ++tile) {
        __syncthreads();
        {
            const float4* W1_4 = (const float4*)(W1 + tile * 256 * 64);
            for (int i = tid; i < 4096; i += THREADS)
                *(float4*)(buf + i * 4) = W1_4[i];
        }
        __syncthreads();

        const float* fbase = feat + tile * 256;
        #pragma unroll 2
        for (int kk = 0; kk < 256; kk += 4) {
            float2 wv[4];
            #pragma unroll
            for (int u = 0; u < 4; ++u)
                wv[u] = *(const float2*)(buf + (kk + u) * 64 + lane * 2);
            #pragma unroll
            for (int r = 0; r < 4; ++r) {
                float4 f = *(const float4*)(fbase + (warp * 4 + r) * FEAT_STRIDE + kk);
                acc[r].x = fmaf(f.x, wv[0].x, acc[r].x); acc[r].y = fmaf(f.x, wv[0].y, acc[r].y);
                acc[r].x = fmaf(f.y, wv[1].x, acc[r].x); acc[r].y = fmaf(f.y, wv[1].y, acc[r].y);
                acc[r].x = fmaf(f.z, wv[2].x, acc[r].x); acc[r].y = fmaf(f.z, wv[2].y, acc[r].y);
                acc[r].x = fmaf(f.w, wv[3].x, acc[r].x); acc[r].y = fmaf(f.w, wv[3].y, acc[r].y);
            }
        }
    }
    #pragma unroll
    for (int r = 0; r < 4; ++r) {
        h1[(warp * 4 + r) * 64 + lane * 2 + 0] = fmaxf(acc[r].x, 0.f);
        h1[(warp * 4 + r) * 64 + lane * 2 + 1] = fmaxf(acc[r].y, 0.f);
    }
    __syncthreads();

    // ---------------- Phase 3: h2 = relu(h1 @ W2) ----------------
    {
        const float4* W2_4 = (const float4*)W2;
        for (int i = tid; i < 1024; i += THREADS)
            *(float4*)(buf + i * 4) = W2_4[i];
    }
    __syncthreads();
    {
        int ray = tid >> 3, c0 = (tid & 7) * 8;
        float a8[8];
        #pragma unroll
        for (int j = 0; j < 8; ++j) a8[j] = 0.f;
        #pragma unroll 4
        for (int k = 0; k < 64; ++k) {
            float hv = h1[ray * 64 + k];
            const float* wrow = buf + k * 64 + c0;
            #pragma unroll
            for (int j = 0; j < 8; ++j)
                a8[j] = fmaf(hv, wrow[j], a8[j]);
        }
        #pragma unroll
        for (int j = 0; j < 8; ++j)
            h2[ray * 64 + c0 + j] = fmaxf(a8[j], 0.f);
    }
    __syncthreads();

    // ---------------- Phase 4: a = h2 @ W3, scale, write out ----------------
    if (tid < 64) {
        int lray = tid >> 1, c = tid & 1;
        int ray = ray0 + lray;
        float a = 0.f;
        #pragma unroll 8
        for (int k = 0; k < 64; ++k)
            a = fmaf(h2[lray * 64 + k], W3[k * 2 + c], a);
        if (c) {
            float dx = endp[ray * 3 + 0] - orig[ray * 3 + 0];
            float dy = endp[ray * 3 + 1] - orig[ray * 3 + 1];
            float dz = endp[ray * 3 + 2] - orig[ray * 3 + 2];
            a *= sqrtf(dx * dx + dy * dy + dz * dz);
        }
        out[ray * 2 + c] = a;
    }
}

extern "C" void kernel_launch(void* const* d_in, const int* in_sizes, int n_in,
                              void* d_out, int out_size) {
    (void)in_sizes; (void)n_in; (void)out_size;
    const float* orig         = (const float*)d_in[0];
    const float* endp         = (const float*)d_in[1];
    const int*   history      = (const int*)d_in[2];
    const float* nodes_min    = (const float*)d_in[3];
    const float* nodes_extent = (const float*)d_in[4];
    const float* emb          = (const float*)d_in[5];
    const float* W1           = (const float*)d_in[6];
    const float* W2           = (const float*)d_in[7];
    const float* W3           = (const float*)d_in[8];
    float*       out          = (float*)d_out;

    static int smem_set = 0;
    if (!smem_set) {
        cudaFuncSetAttribute(nbvh_kernel, cudaFuncAttributeMaxDynamicSharedMemorySize, SMEM_BYTES);
        smem_set = 1;
    }
    nbvh_kernel<<<131072 / RAYS_PER_BLOCK, THREADS, SMEM_BYTES>>>(
        orig, endp, history, nodes_min, nodes_extent, emb, W1, W2, W3, out);
}

// round 3
// speedup vs baseline: 1.7606x; 1.7606x over previous
#include <cuda_runtime.h>
#include <cstdint>

#define RAYS 32
#define THREADS 512
#define ESTRIDE 132          // padded emb/feat row stride (floats)

// smem layout (floats)
#define OFF_PP     0                      // 256 rows * 8 (pox,poy,poz,pex,pey,pez,pad,pad)
#define OFF_NODES  (OFF_PP + 2048)        // 256 ints
#define OFF_EBUF   (OFF_NODES + 256)      // 2 * 32 * 132
#define OFF_FBUF   (OFF_EBUF + 2*32*ESTRIDE)   // 32 * 132 (also partial-sum buffer)
#define OFF_WBUF   (OFF_FBUF + 32*ESTRIDE)     // 128 * 64
#define OFF_H1     (OFF_WBUF + 8192)      // 32 * 64
#define OFF_H2     (OFF_H1 + 2048)        // 32 * 64
#define SMEM_FLOATS (OFF_H2 + 2048)
#define SMEM_BYTES  (SMEM_FLOATS * 4)     // 109,056 B -> 2 CTAs/SM

__device__ __forceinline__ void cp_async16(uint32_t dst, const void* src) {
    asm volatile("cp.async.cg.shared.global [%0], [%1], 16;\n" :: "r"(dst), "l"(src));
}
__device__ __forceinline__ void cp_commit() {
    asm volatile("cp.async.commit_group;\n");
}
__device__ __forceinline__ void cp_wait0() {
    asm volatile("cp.async.wait_group 0;\n");
}
__device__ __forceinline__ uint32_t smem_u32(const void* p) {
    uint32_t a;
    asm("{ .reg .u64 t; cvta.to.shared.u64 t, %1; cvt.u32.u64 %0, t; }" : "=r"(a) : "l"(p));
    return a;
}

__global__ void __launch_bounds__(THREADS, 2) nbvh_kernel(
    const float* __restrict__ orig, const float* __restrict__ endp,
    const int* __restrict__ history32,
    const float* __restrict__ nodes_min, const float* __restrict__ nodes_extent,
    const float* __restrict__ emb,
    const float* __restrict__ W1, const float* __restrict__ W2,
    const float* __restrict__ W3,
    float* __restrict__ out)
{
    extern __shared__ float sm[];
    float* pp    = sm + OFF_PP;
    int*   nodes = (int*)(sm + OFF_NODES);
    float* ebuf  = sm + OFF_EBUF;
    float* fbuf  = sm + OFF_FBUF;
    float* wbuf  = sm + OFF_WBUF;
    float* h1    = sm + OFF_H1;
    float* h2    = sm + OFF_H2;

    const int tid  = threadIdx.x;
    const int ray0 = blockIdx.x * RAYS;

    // history dtype: int64 little-endian (hi words zero since idx < 2^19) vs int32
    const int hstride =
        (history32[1] == 0 && history32[3] == 0 &&
         history32[5] == 0 && history32[7] == 0) ? 2 : 1;

    // ---- precompute per-(ray,depth) clipped entry/exit points + node ids ----
    if (tid < 256) {
        int lr = tid >> 3, d = tid & 7;
        int ray = ray0 + lr;
        int node = history32[(size_t)(ray * 8 + d) * hstride];
        nodes[tid] = node;

        float nx = nodes_min[node * 3 + 0], ny = nodes_min[node * 3 + 1], nz = nodes_min[node * 3 + 2];
        float sx = nodes_extent[node * 3 + 0], sy = nodes_extent[node * 3 + 1], sz = nodes_extent[node * 3 + 2];
        float ox = orig[ray * 3 + 0], oy = orig[ray * 3 + 1], oz = orig[ray * 3 + 2];
        float ex = endp[ray * 3 + 0], ey = endp[ray * 3 + 1], ez = endp[ray * 3 + 2];

        float* q = pp + tid * 8;
        q[0] = fminf(fmaxf((ox - nx) / sx, 0.f), 1.f);
        q[1] = fminf(fmaxf((oy - ny) / sy, 0.f), 1.f);
        q[2] = fminf(fmaxf((oz - nz) / sz, 0.f), 1.f);
        q[3] = fminf(fmaxf((ex - nx) / sx, 0.f), 1.f);
        q[4] = fminf(fmaxf((ey - ny) / sy, 0.f), 1.f);
        q[5] = fminf(fmaxf((ez - nz) / sz, 0.f), 1.f);
    }
    __syncthreads();

    // ---- prefetch emb rows for d=0 (32 rows x 512B), stage W1 tile 0 ----
    {
        // 1024 16B chunks, 2 per thread
        #pragma unroll
        for (int it = 0; it < 2; ++it) {
            int i = tid + it * THREADS;
            int row = i >> 5, l = i & 31;
            const float* src = emb + (size_t)nodes[row * 8 + 0] * 128 + l * 4;
            cp_async16(smem_u32(ebuf + row * ESTRIDE + l * 4), src);
        }
        cp_commit();

        const float4* w4 = (const float4*)W1;   // tile 0
        float4* wd = (float4*)wbuf;
        #pragma unroll
        for (int it = 0; it < 4; ++it)
            wd[tid + it * THREADS] = w4[tid + it * THREADS];

        cp_wait0();
    }
    __syncthreads();

    const int w    = tid >> 5;
    const int lane = tid & 31;
    const int r0   = (w & 7) * 4;
    const int kb   = (w >> 3) * 64;

    float2 acc[4];
    #pragma unroll
    for (int r = 0; r < 4; ++r) acc[r] = make_float2(0.f, 0.f);

    // interp thread mapping
    const int ilr = tid >> 4;          // ray 0..31
    const int isub = tid & 15;
    const int ipp = isub & 7;          // sample point
    const int ifh = isub >> 3;         // feature half (8 floats)

    for (int d = 0; d < 8; ++d) {
        float* ecur = ebuf + (d & 1) * 32 * ESTRIDE;

        // prefetch emb for d+1 into other buffer
        if (d < 7) {
            float* enx = ebuf + ((d + 1) & 1) * 32 * ESTRIDE;
            #pragma unroll
            for (int it = 0; it < 2; ++it) {
                int i = tid + it * THREADS;
                int row = i >> 5, l = i & 31;
                const float* src = emb + (size_t)nodes[row * 8 + d + 1] * 128 + l * 4;
                cp_async16(smem_u32(enx + row * ESTRIDE + l * 4), src);
            }
            cp_commit();
        }

        // ---- interp: 16 threads per ray, each does one p and 8 feature floats ----
        {
            const float* q = pp + (ilr * 8 + d) * 8;
            float pox = q[0], poy = q[1], poz = q[2];
            float t = (float)ipp * (1.0f / 7.0f);
            float x = pox + (q[3] - pox) * t;
            float y = poy + (q[4] - poy) * t;
            float z = poz + (q[5] - poz) * t;
            float mx = 1.f - x, my = 1.f - y, mz = 1.f - z;
            float w0 = mx * my * mz, w1v = x * my * mz;
            float w2v = mx * y * mz, w3v = mx * my * z;
            float w4v = x * my * z,  w5v = mx * y * z;
            float w6v = x * y * mz,  w7v = x * y * z;

            const float* er = ecur + ilr * ESTRIDE + ifh * 8;
            float* fr = fbuf + ilr * ESTRIDE + ipp * 16 + ifh * 8;

            #pragma unroll
            for (int g = 0; g < 2; ++g) {
                float4 e[8];
                #pragma unroll
                for (int c = 0; c < 8; ++c)
                    e[c] = *(const float4*)(er + c * 16 + g * 4);
                float4 a;
                #define TRI(cm) a.cm = fmaf(w7v, e[7].cm, fmaf(w6v, e[6].cm, fmaf(w5v, e[5].cm, \
                                fmaf(w4v, e[4].cm, fmaf(w3v, e[3].cm, fmaf(w2v, e[2].cm,       \
                                fmaf(w1v, e[1].cm, w0 * e[0].cm)))))))
                TRI(x); TRI(y); TRI(z); TRI(w);
                #undef TRI
                *(float4*)(fr + g * 4) = a;
            }
        }
        __syncthreads();   // fbuf ready; wbuf holds W1 tile d

        // ---- GEMM accumulate: warp = 4 rays, lane = 2 cols, warpset splits K ----
        {
            const float* fb0 = fbuf + r0 * ESTRIDE;
            #pragma unroll 4
            for (int kk = kb; kk < kb + 64; kk += 4) {
                float2 wv0 = *(const float2*)(wbuf + (kk + 0) * 64 + lane * 2);
                float2 wv1 = *(const float2*)(wbuf + (kk + 1) * 64 + lane * 2);
                float2 wv2 = *(const float2*)(wbuf + (kk + 2) * 64 + lane * 2);
                float2 wv3 = *(const float2*)(wbuf + (kk + 3) * 64 + lane * 2);
                #pragma unroll
                for (int r = 0; r < 4; ++r) {
                    float4 f = *(const float4*)(fb0 + r * ESTRIDE + kk);
                    acc[r].x = fmaf(f.x, wv0.x, acc[r].x); acc[r].y = fmaf(f.x, wv0.y, acc[r].y);
                    acc[r].x = fmaf(f.y, wv1.x, acc[r].x); acc[r].y = fmaf(f.y, wv1.y, acc[r].y);
                    acc[r].x = fmaf(f.z, wv2.x, acc[r].x); acc[r].y = fmaf(f.z, wv2.y, acc[r].y);
                    acc[r].x = fmaf(f.w, wv3.x, acc[r].x); acc[r].y = fmaf(f.w, wv3.y, acc[r].y);
                }
            }
        }
        __syncthreads();   // GEMM done: fbuf + wbuf reusable

        if (d < 7) {
            const float4* w4 = (const float4*)(W1 + (size_t)(d + 1) * 128 * 64);
            float4* wd = (float4*)wbuf;
            #pragma unroll
            for (int it = 0; it < 4; ++it)
                wd[tid + it * THREADS] = w4[tid + it * THREADS];
            cp_wait0();
            __syncthreads();   // wbuf(d+1) + ebuf(d+1) ready
        }
    }

    // ---- reduce K-split partials, relu -> h1 ----
    float* pbuf = fbuf;   // reuse
    if (w >= 8) {
        #pragma unroll
        for (int r = 0; r < 4; ++r)
            *(float2*)(pbuf + (r0 + r) * 64 + lane * 2) = acc[r];
    }
    __syncthreads();
    if (w < 8) {
        #pragma unroll
        for (int r = 0; r < 4; ++r) {
            float2 pv = *(const float2*)(pbuf + (r0 + r) * 64 + lane * 2);
            h1[(r0 + r) * 64 + lane * 2 + 0] = fmaxf(acc[r].x + pv.x, 0.f);
            h1[(r0 + r) * 64 + lane * 2 + 1] = fmaxf(acc[r].y + pv.y, 0.f);
        }
    }
    __syncthreads();

    // ---- h2 = relu(h1 @ W2) ----
    {
        const float4* w4 = (const float4*)W2;
        float4* wd = (float4*)wbuf;
        #pragma unroll
        for (int it = 0; it < 2; ++it)
            wd[tid + it * THREADS] = w4[tid + it * THREADS];
    }
    __syncthreads();
    {
        int ray = tid >> 4, c0 = (tid & 15) * 4;
        float a0 = 0.f, a1 = 0.f, a2 = 0.f, a3 = 0.f;
        #pragma unroll 8
        for (int k = 0; k < 64; ++k) {
            float hv = h1[ray * 64 + k];
            const float* wr = wbuf + k * 64 + c0;
            a0 = fmaf(hv, wr[0], a0);
            a1 = fmaf(hv, wr[1], a1);
            a2 = fmaf(hv, wr[2], a2);
            a3 = fmaf(hv, wr[3], a3);
        }
        h2[ray * 64 + c0 + 0] = fmaxf(a0, 0.f);
        h2[ray * 64 + c0 + 1] = fmaxf(a1, 0.f);
        h2[ray * 64 + c0 + 2] = fmaxf(a2, 0.f);
        h2[ray * 64 + c0 + 3] = fmaxf(a3, 0.f);
    }
    __syncthreads();

    // ---- out = (h2 @ W3) with dist scaling ----
    if (tid < 64) {
        int lray = tid >> 1, c = tid & 1;
        int ray = ray0 + lray;
        float a = 0.f;
        #pragma unroll 8
        for (int k = 0; k < 64; ++k)
            a = fmaf(h2[lray * 64 + k], W3[k * 2 + c], a);
        if (c) {
            float dx = endp[ray * 3 + 0] - orig[ray * 3 + 0];
            float dy = endp[ray * 3 + 1] - orig[ray * 3 + 1];
            float dz = endp[ray * 3 + 2] - orig[ray * 3 + 2];
            a *= sqrtf(dx * dx + dy * dy + dz * dz);
        }
        out[ray * 2 + c] = a;
    }
}

extern "C" void kernel_launch(void* const* d_in, const int* in_sizes, int n_in,
                              void* d_out, int out_size) {
    (void)in_sizes; (void)n_in; (void)out_size;
    const float* orig         = (const float*)d_in[0];
    const float* endp         = (const float*)d_in[1];
    const int*   history      = (const int*)d_in[2];
    const float* nodes_min    = (const float*)d_in[3];
    const float* nodes_extent = (const float*)d_in[4];
    const float* emb          = (const float*)d_in[5];
    const float* W1           = (const float*)d_in[6];
    const float* W2           = (const float*)d_in[7];
    const float* W3           = (const float*)d_in[8];
    float*       out          = (float*)d_out;

    static int smem_set = 0;
    if (!smem_set) {
        cudaFuncSetAttribute(nbvh_kernel, cudaFuncAttributeMaxDynamicSharedMemorySize, SMEM_BYTES);
        smem_set = 1;
    }
    nbvh_kernel<<<131072 / RAYS, THREADS, SMEM_BYTES>>>(
        orig, endp, history, nodes_min, nodes_extent, emb, W1, W2, W3, out);
}

// round 6
// speedup vs baseline: 2.0259x; 1.1507x over previous
#include <cuda_runtime.h>
#include <cstdint>

#define RAYS 32
#define THREADS 512
#define ESTRIDE 132          // padded emb/feat row stride (floats)

// smem layout (floats)
#define OFF_PP     0                           // 256 rows * 8
#define OFF_NODES  (OFF_PP + 2048)             // 256 ints
#define OFF_EBUF   (OFF_NODES + 256)           // 2 * 32 * 132
#define OFF_FBUF   (OFF_EBUF + 2*32*ESTRIDE)   // 32 * 132
#define OFF_WBUF   (OFF_FBUF + 32*ESTRIDE)     // 128 * 64 (also partial buffer)
#define OFF_H1     (OFF_WBUF + 8192)           // 32 * 64
#define OFF_H2     (OFF_H1 + 2048)             // 32 * 64
#define SMEM_FLOATS (OFF_H2 + 2048)
#define SMEM_BYTES  (SMEM_FLOATS * 4)          // 109,056 B -> 2 CTAs/SM

// ---- packed f32x2 helpers ----
#define FMA2(d, a, b) asm("fma.rn.f32x2 %0, %1, %2, %0;" : "+l"(d) : "l"(a), "l"(b))
#define MUL2(d, a, b) asm("mul.rn.f32x2 %0, %1, %2;"     : "=l"(d) : "l"(a), "l"(b))
#define PACK2(d, s)   asm("mov.b64 %0, {%1, %1};"        : "=l"(d) : "r"(s))
#define UNPK2(lo, hi, d) asm("mov.b64 {%0, %1}, %2;" : "=f"(lo), "=f"(hi) : "l"(d))

__device__ __forceinline__ void cp_async16(uint32_t dst, const void* src) {
    asm volatile("cp.async.cg.shared.global [%0], [%1], 16;\n" :: "r"(dst), "l"(src));
}
__device__ __forceinline__ void cp_commit() { asm volatile("cp.async.commit_group;\n"); }
__device__ __forceinline__ void cp_wait0()  { asm volatile("cp.async.wait_group 0;\n"); }
__device__ __forceinline__ uint32_t smem_u32(const void* p) {
    uint32_t a;
    asm("{ .reg .u64 t; cvta.to.shared.u64 t, %1; cvt.u32.u64 %0, t; }" : "=r"(a) : "l"(p));
    return a;
}

__global__ void __launch_bounds__(THREADS, 2) nbvh_kernel(
    const float* __restrict__ orig, const float* __restrict__ endp,
    const int* __restrict__ history32,
    const float* __restrict__ nodes_min, const float* __restrict__ nodes_extent,
    const float* __restrict__ emb,
    const float* __restrict__ W1, const float* __restrict__ W2,
    const float* __restrict__ W3,
    float* __restrict__ out)
{
    extern __shared__ float sm[];
    float* pp    = sm + OFF_PP;
    int*   nodes = (int*)(sm + OFF_NODES);
    float* ebuf  = sm + OFF_EBUF;
    float* fbuf  = sm + OFF_FBUF;
    float* wbuf  = sm + OFF_WBUF;
    float* h1    = sm + OFF_H1;
    float* h2    = sm + OFF_H2;

    const int tid  = threadIdx.x;
    const int ray0 = blockIdx.x * RAYS;

    // history dtype: int64 little-endian (hi words zero, idx < 2^19) vs int32
    const int hstride =
        (history32[1] == 0 && history32[3] == 0 &&
         history32[5] == 0 && history32[7] == 0) ? 2 : 1;

    // ---- per-(ray,depth) clipped entry/exit + node ids ----
    if (tid < 256) {
        int lr = tid >> 3, d = tid & 7;
        int ray = ray0 + lr;
        int node = history32[(size_t)(ray * 8 + d) * hstride];
        nodes[tid] = node;

        float nx = nodes_min[node * 3 + 0], ny = nodes_min[node * 3 + 1], nz = nodes_min[node * 3 + 2];
        float sx = nodes_extent[node * 3 + 0], sy = nodes_extent[node * 3 + 1], sz = nodes_extent[node * 3 + 2];
        float ox = orig[ray * 3 + 0], oy = orig[ray * 3 + 1], oz = orig[ray * 3 + 2];
        float ex = endp[ray * 3 + 0], ey = endp[ray * 3 + 1], ez = endp[ray * 3 + 2];

        float* q = pp + tid * 8;
        q[0] = fminf(fmaxf((ox - nx) / sx, 0.f), 1.f);
        q[1] = fminf(fmaxf((oy - ny) / sy, 0.f), 1.f);
        q[2] = fminf(fmaxf((oz - nz) / sz, 0.f), 1.f);
        q[3] = fminf(fmaxf((ex - nx) / sx, 0.f), 1.f);
        q[4] = fminf(fmaxf((ey - ny) / sy, 0.f), 1.f);
        q[5] = fminf(fmaxf((ez - nz) / sz, 0.f), 1.f);
    }
    __syncthreads();

    // ---- prefetch emb rows for d=0, stage W1 tile 0 ----
    {
        #pragma unroll
        for (int it = 0; it < 2; ++it) {
            int i = tid + it * THREADS;
            int row = i >> 5, l = i & 31;
            const float* src = emb + (size_t)nodes[row * 8 + 0] * 128 + l * 4;
            cp_async16(smem_u32(ebuf + row * ESTRIDE + l * 4), src);
        }
        cp_commit();

        const float4* w4 = (const float4*)W1;
        float4* wd = (float4*)wbuf;
        #pragma unroll
        for (int it = 0; it < 4; ++it)
            wd[tid + it * THREADS] = w4[tid + it * THREADS];

        cp_wait0();
    }
    __syncthreads();

    // GEMM mapping: warp covers 8 rays x 64 cols; 4-way K split.
    const int w     = tid >> 5;
    const int lane  = tid & 31;
    const int rg    = w & 3;            // ray group: rays rg*8 .. rg*8+7
    const int ks    = w >> 2;           // K split 0..3 (32 k each per depth)
    const int kb    = ks * 32;
    const int rh    = lane >> 4;        // ray half within group
    const int c0    = (lane & 15) * 4;  // 4 cols
    const int rbase = rg * 8 + rh * 4;  // 4 rays per lane

    unsigned long long acc[4][2];
    #pragma unroll
    for (int r = 0; r < 4; ++r) { acc[r][0] = 0ULL; acc[r][1] = 0ULL; }

    // interp thread mapping: 16 threads per ray
    const int ilr = tid >> 4;
    const int isub = tid & 15;
    const int ipp = isub & 7;
    const int ifh = isub >> 3;

    for (int d = 0; d < 8; ++d) {
        float* ecur = ebuf + (d & 1) * 32 * ESTRIDE;

        if (d < 7) {
            float* enx = ebuf + ((d + 1) & 1) * 32 * ESTRIDE;
            #pragma unroll
            for (int it = 0; it < 2; ++it) {
                int i = tid + it * THREADS;
                int row = i >> 5, l = i & 31;
                const float* src = emb + (size_t)nodes[row * 8 + d + 1] * 128 + l * 4;
                cp_async16(smem_u32(enx + row * ESTRIDE + l * 4), src);
            }
            cp_commit();
        }

        // ---- interp (packed f32x2) ----
        {
            const float* q = pp + (ilr * 8 + d) * 8;
            float pox = q[0], poy = q[1], poz = q[2];
            float t = (float)ipp * (1.0f / 7.0f);
            float x = pox + (q[3] - pox) * t;
            float y = poy + (q[4] - poy) * t;
            float z = poz + (q[5] - poz) * t;
            float mx = 1.f - x, my = 1.f - y, mz = 1.f - z;
            float wsc[8];
            wsc[0] = mx * my * mz; wsc[1] = x * my * mz;
            wsc[2] = mx * y * mz;  wsc[3] = mx * my * z;
            wsc[4] = x * my * z;   wsc[5] = mx * y * z;
            wsc[6] = x * y * mz;   wsc[7] = x * y * z;
            unsigned long long pw[8];
            #pragma unroll
            for (int c = 0; c < 8; ++c) PACK2(pw[c], __float_as_uint(wsc[c]));

            const float* er = ecur + ilr * ESTRIDE + ifh * 8;
            float* fr = fbuf + ilr * ESTRIDE + ipp * 16 + ifh * 8;

            #pragma unroll
            for (int g = 0; g < 2; ++g) {
                ulonglong2 e[8];
                #pragma unroll
                for (int c = 0; c < 8; ++c)
                    e[c] = *(const ulonglong2*)(er + c * 16 + g * 4);
                unsigned long long a0, a1;
                MUL2(a0, pw[0], e[0].x);
                MUL2(a1, pw[0], e[0].y);
                #pragma unroll
                for (int c = 1; c < 8; ++c) {
                    FMA2(a0, pw[c], e[c].x);
                    FMA2(a1, pw[c], e[c].y);
                }
                ulonglong2 res; res.x = a0; res.y = a1;
                *(ulonglong2*)(fr + g * 4) = res;
            }
        }
        __syncthreads();   // fbuf ready; wbuf holds W1 tile d

        // ---- GEMM accumulate (packed f32x2) ----
        {
            const float* fb0 = fbuf + rbase * ESTRIDE;
            #pragma unroll 2
            for (int kk = kb; kk < kb + 32; kk += 4) {
                ulonglong2 wv[4];
                #pragma unroll
                for (int u = 0; u < 4; ++u)
                    wv[u] = *(const ulonglong2*)(wbuf + (kk + u) * 64 + c0);
                #pragma unroll
                for (int r = 0; r < 4; ++r) {
                    float4 f = *(const float4*)(fb0 + r * ESTRIDE + kk);
                    unsigned long long fp;
                    PACK2(fp, __float_as_uint(f.x));
                    FMA2(acc[r][0], fp, wv[0].x); FMA2(acc[r][1], fp, wv[0].y);
                    PACK2(fp, __float_as_uint(f.y));
                    FMA2(acc[r][0], fp, wv[1].x); FMA2(acc[r][1], fp, wv[1].y);
                    PACK2(fp, __float_as_uint(f.z));
                    FMA2(acc[r][0], fp, wv[2].x); FMA2(acc[r][1], fp, wv[2].y);
                    PACK2(fp, __float_as_uint(f.w));
                    FMA2(acc[r][0], fp, wv[3].x); FMA2(acc[r][1], fp, wv[3].y);
                }
            }
        }
        __syncthreads();   // GEMM done: fbuf + wbuf reusable

        if (d < 7) {
            const float4* w4 = (const float4*)(W1 + (size_t)(d + 1) * 128 * 64);
            float4* wd = (float4*)wbuf;
            #pragma unroll
            for (int it = 0; it < 4; ++it)
                wd[tid + it * THREADS] = w4[tid + it * THREADS];
            cp_wait0();
            __syncthreads();
        }
    }

    // ---- reduce 4-way K-split partials, relu -> h1 ----
    float* pbuf = wbuf;   // 3 * 2048 floats
    if (ks > 0) {
        #pragma unroll
        for (int r = 0; r < 4; ++r) {
            float* dst = pbuf + (ks - 1) * 2048 + (rbase + r) * 64 + c0;
            float l0, h0, l1, h1v;
            UNPK2(l0, h0, acc[r][0]);
            UNPK2(l1, h1v, acc[r][1]);
            dst[0] = l0; dst[1] = h0; dst[2] = l1; dst[3] = h1v;
        }
    }
    __syncthreads();
    if (ks == 0) {
        #pragma unroll
        for (int r = 0; r < 4; ++r) {
            float l0, h0, l1, h1v;
            UNPK2(l0, h0, acc[r][0]);
            UNPK2(l1, h1v, acc[r][1]);
            const float* p0 = pbuf + 0 * 2048 + (rbase + r) * 64 + c0;
            const float* p1 = pbuf + 1 * 2048 + (rbase + r) * 64 + c0;
            const float* p2 = pbuf + 2 * 2048 + (rbase + r) * 64 + c0;
            float* dst = h1 + (rbase + r) * 64 + c0;
            dst[0] = fmaxf(l0  + p0[0] + p1[0] + p2[0], 0.f);
            dst[1] = fmaxf(h0  + p0[1] + p1[1] + p2[1], 0.f);
            dst[2] = fmaxf(l1  + p0[2] + p1[2] + p2[2], 0.f);
            dst[3] = fmaxf(h1v + p0[3] + p1[3] + p2[3], 0.f);
        }
    }
    __syncthreads();

    // ---- h2 = relu(h1 @ W2), packed ----
    {
        const float4* w4 = (const float4*)W2;
        float4* wd = (float4*)wbuf;
        #pragma unroll
        for (int it = 0; it < 2; ++it)
            wd[tid + it * THREADS] = w4[tid + it * THREADS];
    }
    __syncthreads();
    {
        int ray = tid >> 4, cc0 = (tid & 15) * 4;
        unsigned long long a01 = 0ULL, a23 = 0ULL;
        #pragma unroll 8
        for (int k = 0; k < 64; ++k) {
            float hv = h1[ray * 64 + k];
            unsigned long long hp;
            PACK2(hp, __float_as_uint(hv));
            ulonglong2 wp = *(const ulonglong2*)(wbuf + k * 64 + cc0);
            FMA2(a01, hp, wp.x);
            FMA2(a23, hp, wp.y);
        }
        float v0, v1, v2, v3;
        UNPK2(v0, v1, a01);
        UNPK2(v2, v3, a23);
        h2[ray * 64 + cc0 + 0] = fmaxf(v0, 0.f);
        h2[ray * 64 + cc0 + 1] = fmaxf(v1, 0.f);
        h2[ray * 64 + cc0 + 2] = fmaxf(v2, 0.f);
        h2[ray * 64 + cc0 + 3] = fmaxf(v3, 0.f);
    }
    __syncthreads();

    // ---- out = (h2 @ W3) with dist scaling ----
    if (tid < 64) {
        int lray = tid >> 1, c = tid & 1;
        int ray = ray0 + lray;
        float a = 0.f;
        #pragma unroll 8
        for (int k = 0; k < 64; ++k)
            a = fmaf(h2[lray * 64 + k], W3[k * 2 + c], a);
        if (c) {
            float dx = endp[ray * 3 + 0] - orig[ray * 3 + 0];
            float dy = endp[ray * 3 + 1] - orig[ray * 3 + 1];
            float dz = endp[ray * 3 + 2] - orig[ray * 3 + 2];
            a *= sqrtf(dx * dx + dy * dy + dz * dz);
        }
        out[ray * 2 + c] = a;
    }
}

extern "C" void kernel_launch(void* const* d_in, const int* in_sizes, int n_in,
                              void* d_out, int out_size) {
    (void)in_sizes; (void)n_in; (void)out_size;
    const float* orig         = (const float*)d_in[0];
    const float* endp         = (const float*)d_in[1];
    const int*   history      = (const int*)d_in[2];
    const float* nodes_min    = (const float*)d_in[3];
    const float* nodes_extent = (const float*)d_in[4];
    const float* emb          = (const float*)d_in[5];
    const float* W1           = (const float*)d_in[6];
    const float* W2           = (const float*)d_in[7];
    const float* W3           = (const float*)d_in[8];
    float*       out          = (float*)d_out;

    static int smem_set = 0;
    if (!smem_set) {
        cudaFuncSetAttribute(nbvh_kernel, cudaFuncAttributeMaxDynamicSharedMemorySize, SMEM_BYTES);
        smem_set = 1;
    }
    nbvh_kernel<<<131072 / RAYS, THREADS, SMEM_BYTES>>>(
        orig, endp, history, nodes_min, nodes_extent, emb, W1, W2, W3, out);
}

// round 14
// speedup vs baseline: 3.6944x; 1.8236x over previous
#include <cuda_runtime.h>
#include <cuda_bf16.h>
#include <cstdint>

#define N_RAYS 131072
#define IN_DIM 1024

// ---- global scratch (static: no runtime allocation) ----
__device__ __nv_bfloat16 g_feat_hi[(size_t)N_RAYS * IN_DIM];
__device__ __nv_bfloat16 g_feat_lo[(size_t)N_RAYS * IN_DIM];
__device__ __nv_bfloat16 g_w1t_hi[64 * IN_DIM];   // [n][k]
__device__ __nv_bfloat16 g_w1t_lo[64 * IN_DIM];

// ---- packed f32x2 helpers ----
#define FMA2(d, a, b) asm("fma.rn.f32x2 %0, %1, %2, %0;" : "+l"(d) : "l"(a), "l"(b))
#define MUL2(d, a, b) asm("mul.rn.f32x2 %0, %1, %2;"     : "=l"(d) : "l"(a), "l"(b))
#define PACK2(d, s)   asm("mov.b64 %0, {%1, %1};"        : "=l"(d) : "r"(s))
#define UNPK2(lo, hi, d) asm("mov.b64 {%0, %1}, %2;" : "=f"(lo), "=f"(hi) : "l"(d))

__device__ __forceinline__ void cp_async16(uint32_t dst, const void* src) {
    asm volatile("cp.async.cg.shared.global [%0], [%1], 16;\n" :: "r"(dst), "l"(src));
}
__device__ __forceinline__ void cp_commit() { asm volatile("cp.async.commit_group;\n"); }
__device__ __forceinline__ void cp_wait0()  { asm volatile("cp.async.wait_group 0;\n"); }
__device__ __forceinline__ void cp_wait1()  { asm volatile("cp.async.wait_group 1;\n"); }
__device__ __forceinline__ uint32_t smem_u32(const void* p) {
    uint32_t a;
    asm("{ .reg .u64 t; cvta.to.shared.u64 t, %1; cvt.u32.u64 %0, t; }" : "=r"(a) : "l"(p));
    return a;
}

// mma.sync m16n8k16 bf16 (baseline PTX, compiles for sm_103 non-'a')
#define MMA_BF16(d, a, b) \
    asm volatile("mma.sync.aligned.m16n8k16.row.col.f32.bf16.bf16.f32 " \
        "{%0,%1,%2,%3}, {%4,%5,%6,%7}, {%8,%9}, {%0,%1,%2,%3};" \
        : "+f"((d)[0]), "+f"((d)[1]), "+f"((d)[2]), "+f"((d)[3]) \
        : "r"((a)[0]), "r"((a)[1]), "r"((a)[2]), "r"((a)[3]), \
          "r"((b)[0]), "r"((b)[1]))

__device__ __forceinline__ void ldsm4(uint32_t* r, uint32_t addr) {
    asm volatile("ldmatrix.sync.aligned.m8n8.x4.shared.b16 {%0,%1,%2,%3}, [%4];"
        : "=r"(r[0]), "=r"(r[1]), "=r"(r[2]), "=r"(r[3]) : "r"(addr));
}

// ===================================================================
// Kernel 0: transpose W1 -> bf16 hi/lo planes [n][k]
// ===================================================================
__global__ void prep_w(const float* __restrict__ W1) {
    int idx = blockIdx.x * 1024 + threadIdx.x;   // 64n * 1024k
    int n = idx >> 10, k = idx & 1023;
    float v = W1[k * 64 + n];
    __nv_bfloat16 hi = __float2bfloat16(v);
    __nv_bfloat16 lo = __float2bfloat16(v - __bfloat162float(hi));
    g_w1t_hi[idx] = hi;
    g_w1t_lo[idx] = lo;
}

// ===================================================================
// Kernel 1: gather + trilinear interp -> feat bf16 hi/lo planes
// ===================================================================
#define F_RAYS 32
#define F_THREADS 512
#define ESTRIDE 132
#define OFF_PP     0
#define OFF_NODES  (OFF_PP + 2048)
#define OFF_EBUF   (OFF_NODES + 256)
#define F_SMEM_FLOATS (OFF_EBUF + 2*32*ESTRIDE)
#define F_SMEM_BYTES  (F_SMEM_FLOATS * 4)     // 43,008 B

__global__ void __launch_bounds__(F_THREADS, 3) feat_kernel(
    const float* __restrict__ orig, const float* __restrict__ endp,
    const int* __restrict__ history32,
    const float* __restrict__ nodes_min, const float* __restrict__ nodes_extent,
    const float* __restrict__ emb)
{
    extern __shared__ float sm[];
    float* pp    = sm + OFF_PP;
    int*   nodes = (int*)(sm + OFF_NODES);
    float* ebuf  = sm + OFF_EBUF;

    const int tid  = threadIdx.x;
    const int ray0 = blockIdx.x * F_RAYS;

    const int hstride =
        (history32[1] == 0 && history32[3] == 0 &&
         history32[5] == 0 && history32[7] == 0) ? 2 : 1;

    if (tid < 256) {
        int lr = tid >> 3, d = tid & 7;
        int ray = ray0 + lr;
        int node = history32[(size_t)(ray * 8 + d) * hstride];
        nodes[tid] = node;

        float nx = nodes_min[node * 3 + 0], ny = nodes_min[node * 3 + 1], nz = nodes_min[node * 3 + 2];
        float sx = nodes_extent[node * 3 + 0], sy = nodes_extent[node * 3 + 1], sz = nodes_extent[node * 3 + 2];
        float ox = orig[ray * 3 + 0], oy = orig[ray * 3 + 1], oz = orig[ray * 3 + 2];
        float ex = endp[ray * 3 + 0], ey = endp[ray * 3 + 1], ez = endp[ray * 3 + 2];

        float* q = pp + tid * 8;
        q[0] = fminf(fmaxf((ox - nx) / sx, 0.f), 1.f);
        q[1] = fminf(fmaxf((oy - ny) / sy, 0.f), 1.f);
        q[2] = fminf(fmaxf((oz - nz) / sz, 0.f), 1.f);
        q[3] = fminf(fmaxf((ex - nx) / sx, 0.f), 1.f);
        q[4] = fminf(fmaxf((ey - ny) / sy, 0.f), 1.f);
        q[5] = fminf(fmaxf((ez - nz) / sz, 0.f), 1.f);
    }
    __syncthreads();

    {
        #pragma unroll
        for (int it = 0; it < 2; ++it) {
            int i = tid + it * F_THREADS;
            int row = i >> 5, l = i & 31;
            const float* src = emb + (size_t)nodes[row * 8 + 0] * 128 + l * 4;
            cp_async16(smem_u32(ebuf + row * ESTRIDE + l * 4), src);
        }
        cp_commit();
        cp_wait0();
    }
    __syncthreads();

    const int ilr = tid >> 4;
    const int isub = tid & 15;
    const int ipp = isub & 7;
    const int ifh = isub >> 3;

    for (int d = 0; d < 8; ++d) {
        float* ecur = ebuf + (d & 1) * 32 * ESTRIDE;

        if (d < 7) {
            float* enx = ebuf + ((d + 1) & 1) * 32 * ESTRIDE;
            #pragma unroll
            for (int it = 0; it < 2; ++it) {
                int i = tid + it * F_THREADS;
                int row = i >> 5, l = i & 31;
                const float* src = emb + (size_t)nodes[row * 8 + d + 1] * 128 + l * 4;
                cp_async16(smem_u32(enx + row * ESTRIDE + l * 4), src);
            }
            cp_commit();
        }

        {
            const float* q = pp + (ilr * 8 + d) * 8;
            float pox = q[0], poy = q[1], poz = q[2];
            float t = (float)ipp * (1.0f / 7.0f);
            float x = pox + (q[3] - pox) * t;
            float y = poy + (q[4] - poy) * t;
            float z = poz + (q[5] - poz) * t;
            float mx = 1.f - x, my = 1.f - y, mz = 1.f - z;
            float wsc[8];
            wsc[0] = mx * my * mz; wsc[1] = x * my * mz;
            wsc[2] = mx * y * mz;  wsc[3] = mx * my * z;
            wsc[4] = x * my * z;   wsc[5] = mx * y * z;
            wsc[6] = x * y * mz;   wsc[7] = x * y * z;
            unsigned long long pw[8];
            #pragma unroll
            for (int c = 0; c < 8; ++c) PACK2(pw[c], __float_as_uint(wsc[c]));

            const float* er = ecur + ilr * ESTRIDE + ifh * 8;
            float f[8];

            #pragma unroll
            for (int g = 0; g < 2; ++g) {
                ulonglong2 e[8];
                #pragma unroll
                for (int c = 0; c < 8; ++c)
                    e[c] = *(const ulonglong2*)(er + c * 16 + g * 4);
                unsigned long long a0, a1;
                MUL2(a0, pw[0], e[0].x);
                MUL2(a1, pw[0], e[0].y);
                #pragma unroll
                for (int c = 1; c < 8; ++c) {
                    FMA2(a0, pw[c], e[c].x);
                    FMA2(a1, pw[c], e[c].y);
                }
                UNPK2(f[g * 4 + 0], f[g * 4 + 1], a0);
                UNPK2(f[g * 4 + 2], f[g * 4 + 3], a1);
            }

            union { __nv_bfloat16 h[8]; uint4 q4; } H, L;
            #pragma unroll
            for (int i = 0; i < 8; ++i) {
                H.h[i] = __float2bfloat16(f[i]);
                L.h[i] = __float2bfloat16(f[i] - __bfloat162float(H.h[i]));
            }
            size_t base = (size_t)(ray0 + ilr) * 1024 + d * 128 + ipp * 16 + ifh * 8;
            *(uint4*)(g_feat_hi + base) = H.q4;
            *(uint4*)(g_feat_lo + base) = L.q4;
        }

        if (d < 7) {
            cp_wait0();
            __syncthreads();
        }
    }
}

// ===================================================================
// Kernel 2: mma.sync GEMM (feat@W1 bf16x3, ldmatrix) + SIMT W2/W3
// ===================================================================
#define G_THREADS 256
#define RSTRIDE 144                 // padded row stride (bytes)
#define APLANE  (128 * RSTRIDE)     // 18432
#define BPLANE  (64 * RSTRIDE)      // 9216
#define CHUNK   (2*APLANE + 2*BPLANE)  // 55296
#define S_W3    0
#define S_BUF   4096
#define G_SMEM_BYTES (S_BUF + 2*CHUNK)  // 114,688
#define H1S 68                      // h1 smem row stride (floats)

__global__ void __launch_bounds__(G_THREADS) gemm_kernel(
    const float* __restrict__ orig, const float* __restrict__ endp,
    const float* __restrict__ W2, const float* __restrict__ W3,
    float* __restrict__ out)
{
    extern __shared__ char smc[];
    const uint32_t smem_base = smem_u32(smc);
    float* sw3 = (float*)(smc + S_W3);

    const int tid  = threadIdx.x;
    const int ray0 = blockIdx.x * 128;
    const int warp = tid >> 5, lane = tid & 31;
    const int wm = warp & 3, wn = warp >> 2;     // warp tile: rows wm*32.., cols wn*32..
    const int gid = lane >> 2, qp = lane & 3;

    // per-thread ldmatrix address offsets (bytes, within a plane)
    const uint32_t aoff = (uint32_t)((wm * 32 + (lane & 15)) * RSTRIDE + (lane >> 4) * 16);
    const uint32_t boff = (uint32_t)((wn * 32 + (lane >> 4) * 8 + (lane & 7)) * RSTRIDE
                                     + ((lane >> 3) & 1) * 16);

    // ---- chunk loader: K-chunk c (64 bf16) into buffer b ----
    auto load_chunk = [&](int c, int b) {
        uint32_t buf = smem_base + S_BUF + b * CHUNK;
        #pragma unroll
        for (int it = 0; it < 4; ++it) {
            int i = tid + it * G_THREADS;
            int row = i >> 3, j = i & 7;
            uint32_t off = row * RSTRIDE + j * 16;
            const size_t src = (size_t)(ray0 + row) * 1024 + c * 64 + j * 8;
            cp_async16(buf + off,          g_feat_hi + src);
            cp_async16(buf + APLANE + off, g_feat_lo + src);
        }
        #pragma unroll
        for (int it = 0; it < 2; ++it) {
            int i = tid + it * G_THREADS;
            int row = i >> 3, j = i & 7;
            uint32_t off = row * RSTRIDE + j * 16;
            const size_t src = (size_t)row * 1024 + c * 64 + j * 8;
            cp_async16(buf + 2 * APLANE + off,          g_w1t_hi + src);
            cp_async16(buf + 2 * APLANE + BPLANE + off, g_w1t_lo + src);
        }
        cp_commit();
    };

    float acc[2][4][4];
    #pragma unroll
    for (int mt = 0; mt < 2; ++mt)
        #pragma unroll
        for (int nt = 0; nt < 4; ++nt)
            #pragma unroll
            for (int v = 0; v < 4; ++v) acc[mt][nt][v] = 0.f;

    load_chunk(0, 0);

    for (int c = 0; c < 16; ++c) {
        if (c < 15) { load_chunk(c + 1, (c + 1) & 1); cp_wait1(); }
        else        { cp_wait0(); }
        __syncthreads();

        uint32_t buf = smem_base + S_BUF + (c & 1) * CHUNK;
        uint32_t ahi = buf, alo = buf + APLANE;
        uint32_t bhi = buf + 2 * APLANE, blo = bhi + BPLANE;

        #pragma unroll
        for (int ks = 0; ks < 4; ++ks) {
            uint32_t kb = ks * 32;   // 16 bf16 = 32 bytes
            uint32_t aH[2][4], aL[2][4], bH[8], bL[8];
            #pragma unroll
            for (int mt = 0; mt < 2; ++mt) {
                ldsm4(aH[mt], ahi + aoff + mt * 16 * RSTRIDE + kb);
                ldsm4(aL[mt], alo + aoff + mt * 16 * RSTRIDE + kb);
            }
            #pragma unroll
            for (int np = 0; np < 2; ++np) {
                ldsm4(bH + np * 4, bhi + boff + np * 16 * RSTRIDE + kb);
                ldsm4(bL + np * 4, blo + boff + np * 16 * RSTRIDE + kb);
            }
            #pragma unroll
            for (int mt = 0; mt < 2; ++mt)
                #pragma unroll
                for (int nt = 0; nt < 4; ++nt) {
                    MMA_BF16(acc[mt][nt], aH[mt], bH + nt * 2);
                    MMA_BF16(acc[mt][nt], aL[mt], bH + nt * 2);
                    MMA_BF16(acc[mt][nt], aH[mt], bL + nt * 2);
                }
        }
        __syncthreads();
    }

    // ---- h1 (relu, fp32) -> smem; stage W2/W3 fp32 ----
    float* h1buf = (float*)(smc + S_BUF);                 // 128 x H1S floats (34,816 B)
    float* wbuf  = (float*)(smc + S_BUF + CHUNK);         // 4096 floats (16 KB)
    #pragma unroll
    for (int mt = 0; mt < 2; ++mt)
        #pragma unroll
        for (int nt = 0; nt < 4; ++nt) {
            int row = wm * 32 + mt * 16 + gid;
            int col = wn * 32 + nt * 8 + qp * 2;
            #pragma unroll
            for (int half = 0; half < 2; ++half) {
                float2 v;
                v.x = fmaxf(acc[mt][nt][half * 2 + 0], 0.f);
                v.y = fmaxf(acc[mt][nt][half * 2 + 1], 0.f);
                *(float2*)(h1buf + (row + half * 8) * H1S + col) = v;
            }
        }
    {
        const float4* w4 = (const float4*)W2;
        float4* wd = (float4*)wbuf;
        #pragma unroll
        for (int it = 0; it < 4; ++it)
            wd[tid + it * G_THREADS] = w4[tid + it * G_THREADS];
        if (tid < 128) sw3[tid] = W3[tid];
    }
    __syncthreads();

    // ---- SIMT fp32: h2 = relu(h1 @ W2); out = h2 @ W3 (dist scaled) ----
    {
        int lray = tid >> 1, half = tid & 1, c0 = half * 32;
        float a32[32];
        #pragma unroll
        for (int j = 0; j < 32; ++j) a32[j] = 0.f;
        #pragma unroll 4
        for (int k = 0; k < 64; ++k) {
            float hv = h1buf[lray * H1S + k];
            const float* wr = wbuf + k * 64 + c0;
            #pragma unroll
            for (int j = 0; j < 32; ++j)
                a32[j] = fmaf(hv, wr[j], a32[j]);
        }
        float o0 = 0.f, o1 = 0.f;
        #pragma unroll
        for (int j = 0; j < 32; ++j) {
            float v = fmaxf(a32[j], 0.f);
            int col = c0 + j;
            o0 = fmaf(v, sw3[col * 2 + 0], o0);
            o1 = fmaf(v, sw3[col * 2 + 1], o1);
        }
        o0 += __shfl_xor_sync(0xFFFFFFFFu, o0, 1);
        o1 += __shfl_xor_sync(0xFFFFFFFFu, o1, 1);
        if (half == 0) {
            int ray = ray0 + lray;
            float dx = endp[ray * 3 + 0] - orig[ray * 3 + 0];
            float dy = endp[ray * 3 + 1] - orig[ray * 3 + 1];
            float dz = endp[ray * 3 + 2] - orig[ray * 3 + 2];
            float len = sqrtf(dx * dx + dy * dy + dz * dz);
            out[ray * 2 + 0] = o0;
            out[ray * 2 + 1] = o1 * len;
        }
    }
}

// ===================================================================
extern "C" void kernel_launch(void* const* d_in, const int* in_sizes, int n_in,
                              void* d_out, int out_size) {
    (void)in_sizes; (void)n_in; (void)out_size;
    const float* orig         = (const float*)d_in[0];
    const float* endp         = (const float*)d_in[1];
    const int*   history      = (const int*)d_in[2];
    const float* nodes_min    = (const float*)d_in[3];
    const float* nodes_extent = (const float*)d_in[4];
    const float* emb          = (const float*)d_in[5];
    const float* W1           = (const float*)d_in[6];
    const float* W2           = (const float*)d_in[7];
    const float* W3           = (const float*)d_in[8];
    float*       out          = (float*)d_out;

    static int inited = 0;
    if (!inited) {
        cudaFuncSetAttribute(feat_kernel, cudaFuncAttributeMaxDynamicSharedMemorySize, F_SMEM_BYTES);
        cudaFuncSetAttribute(gemm_kernel, cudaFuncAttributeMaxDynamicSharedMemorySize, G_SMEM_BYTES);
        inited = 1;
    }

    prep_w<<<64, 1024>>>(W1);
    feat_kernel<<<N_RAYS / F_RAYS, F_THREADS, F_SMEM_BYTES>>>(
        orig, endp, history, nodes_min, nodes_extent, emb);
    gemm_kernel<<<N_RAYS / 128, G_THREADS, G_SMEM_BYTES>>>(
        orig, endp, W2, W3, out);
}